// round 9
// baseline (speedup 1.0000x reference)
#include <cuda_runtime.h>
#include <cuda_fp16.h>
#include <cstdint>

#define NTOK 65536
#define MT 64
#define MAXTILE 1040
#define NSM 148

// byte offsets in dynamic smem (k_layer)
#define SM_X    0         // 64*68 half2 words = 17408 B
#define SM_B    17408     // 131072 B weight buffer (one layer, one expert)
#define SM_BIAS 148480    // 512 floats
#define SM_TOK  150528    // 64 ints
#define SMEM_MAIN 150784

__device__ int g_cnt[9];          // zero at program start; re-zeroed by k_layer<1>
__device__ int g_ntiles;
__device__ unsigned g_done;       // monotonically increasing epoch counter
__device__ int g_tok[9 * NTOK];
__device__ int g_te[MAXTILE], g_ts[MAXTILE], g_tn[MAXTILE];
// fragment-ordered fp16 weights: per (l,e): 32768 words
// word = ks*4096 + g*1024 + nh*512 + ntp*128 + lane*4 + q   (ks = 0..7)
__device__ __align__(16) uint32_t g_Wf[18 * 32768];
// layer-0 output, fp16 pairs, tile-major: [tile][r(64)][c2(64)]
__device__ __align__(16) uint32_t g_Xmid[(size_t)MAXTILE * 4096];

__device__ __forceinline__ float tanha(float x) {
    float r; asm("tanh.approx.f32 %0,%1;" : "=f"(r) : "f"(x)); return r;
}
__device__ __forceinline__ float sigf(float v) {
    return fmaf(0.5f, tanha(0.5f * v), 0.5f);
}
__device__ __forceinline__ void mma16(float* c, const uint32_t* a, uint32_t b0, uint32_t b1) {
    asm volatile(
        "mma.sync.aligned.m16n8k16.row.col.f32.f16.f16.f32 "
        "{%0,%1,%2,%3},{%4,%5,%6,%7},{%8,%9},{%0,%1,%2,%3};"
        : "+f"(c[0]), "+f"(c[1]), "+f"(c[2]), "+f"(c[3])
        : "r"(a[0]), "r"(a[1]), "r"(a[2]), "r"(a[3]), "r"(b0), "r"(b1));
}
__device__ __forceinline__ uint32_t sptr(const void* p) {
    return (uint32_t)__cvta_generic_to_shared(p);
}
__device__ __forceinline__ void cpa16(uint32_t dst, const void* src) {
    asm volatile("cp.async.cg.shared.global [%0],[%1],16;" :: "r"(dst), "l"(src));
}
__device__ __forceinline__ uint32_t packh2(float a, float b) {
    __half2 h = __floats2half2_rn(a, b);
    return *(uint32_t*)&h;
}

// ---------------- prep: fused wprep (blocks 0..287) + hist/tiles (blocks 288..415) ----
__global__ void k_prep_all(const float* __restrict__ W, const int* __restrict__ pos) {
    int b = blockIdx.x;
    int tid = threadIdx.x;
    if (b < 288) {
        // weight fragment prep: m = b>>2, kg = b&3 handles ks = 2kg..2kg+1
        __shared__ float s[32 * 128];
        int m = b >> 2, kg = b & 3;
        int l = m / 36, g = (m / 9) % 4, e = m % 9;
        const float* src = W + (size_t)m * 16384 + kg * 4096;
        for (int i = tid; i < 4096; i += 512) s[i] = src[i];
        __syncthreads();
        uint32_t* dst = g_Wf + (size_t)(l * 9 + e) * 32768 + g * 1024;
        for (int i = tid; i < 2048; i += 512) {
            int ksl = i >> 10, nh = (i >> 9) & 1;
            int ntp = (i >> 7) & 3, lane = (i >> 2) & 31, q = i & 3;
            int tig = lane & 3, grp = lane >> 2, bsel = q & 1;
            int n = nh * 64 + (ntp * 2 + (q >> 1)) * 8 + grp;
            int k0l = ksl * 16 + bsel * 8 + 2 * tig;
            dst[(kg * 2 + ksl) * 4096 + nh * 512 + ntp * 128 + lane * 4 + q] =
                packh2(s[k0l * 128 + n], s[(k0l + 1) * 128 + n]);
        }
    } else {
        __shared__ int scnt[9], sbase[9];
        __shared__ int amlast;
        __shared__ int ts[10];
        int t = (b - 288) * 512 + tid;
        if (tid < 9) scnt[tid] = 0;
        int probe = t & 8191;
        int bad = (pos[2 * probe + 1] != 0);
        bad = __syncthreads_or(bad);
        int p = bad ? pos[t] : pos[2 * t];
        int e = p > 8 ? 8 : (p < 0 ? 0 : p);
        int my = atomicAdd(&scnt[e], 1);
        __syncthreads();
        if (tid < 9) sbase[tid] = atomicAdd(&g_cnt[tid], scnt[tid]);
        __syncthreads();
        g_tok[e * NTOK + sbase[e] + my] = t;
        __threadfence();
        __syncthreads();
        if (tid == 0) amlast = ((atomicAdd(&g_done, 1u) & 127u) == 127u);
        __syncthreads();
        if (amlast) {
            if (tid == 0) {
                ts[0] = 0;
                for (int ee = 0; ee < 9; ee++) ts[ee + 1] = ts[ee] + ((g_cnt[ee] + MT - 1) / MT);
                g_ntiles = ts[9];
            }
            __syncthreads();
            int n = ts[9];
            for (int tt = tid; tt < n; tt += 512) {
                int ee = 0;
                while (!(tt >= ts[ee] && tt < ts[ee + 1])) ee++;
                int s = (tt - ts[ee]) * MT;
                g_te[tt] = ee; g_ts[tt] = s;
                int rem = g_cnt[ee] - s;
                g_tn[tt] = rem < MT ? rem : MT;
            }
        }
    }
}

// ---------------- per-layer persistent kernel ----------------
template<int L>
__global__ void __launch_bounds__(1024, 1)
k_layer(const float* __restrict__ xin, const float* __restrict__ bs, float* __restrict__ out) {
    extern __shared__ __align__(16) char smc[];
    int tid = threadIdx.x, lane = tid & 31, w = tid >> 5;
    int mh = w >> 3, nq = w & 7;
    int tig = lane & 3, grp = lane >> 2;

    uint32_t* Xs2 = (uint32_t*)smc;
    float* sbias = (float*)(smc + SM_BIAS);
    int* stok = (int*)(smc + SM_TOK);

    int nt_all = g_ntiles;
    int cid = blockIdx.x;
    int base = nt_all / NSM, rem = nt_all % NSM;
    int t0 = cid * base + (cid < rem ? cid : rem);
    int cnt = base + (cid < rem ? 1 : 0);

    int cur_e = -1;
    for (int ti = 0; ti < cnt; ti++) {
        int t = t0 + ti;
        int e = g_te[t], s0 = g_ts[t], nr = g_tn[t];
        bool sw = (e != cur_e);
        cur_e = e;
        if (sw) {
            const uint4* ws = (const uint4*)(g_Wf + (size_t)(L * 9 + e) * 32768);
            uint32_t d = sptr(smc + SM_B);
            #pragma unroll
            for (int i = 0; i < 8; i++)
                cpa16(d + (tid + i * 1024) * 16, ws + tid + i * 1024);
            asm volatile("cp.async.commit_group;");
            if (tid < 512)
                sbias[tid] = bs[((L * 4 + (tid >> 7)) * 9 + e) * 128 + (tid & 127)];
        }
        if (tid < MT) stok[tid] = (tid < nr) ? g_tok[e * NTOK + s0 + tid] : -1;
        __syncthreads();    // stok visible

        if (L == 0) {
            for (int i = tid; i < MT * 32; i += 1024) {
                int r = i >> 5, c4 = i & 31;
                int tk = stok[r];
                float4 v = (tk >= 0) ? ((const float4*)xin)[(size_t)tk * 32 + c4]
                                     : make_float4(0.f, 0.f, 0.f, 0.f);
                Xs2[r * 68 + c4 * 2]     = packh2(v.x, v.y);
                Xs2[r * 68 + c4 * 2 + 1] = packh2(v.z, v.w);
            }
        } else {
            uint4 v = ((const uint4*)g_Xmid)[(size_t)t * 1024 + tid];
            int r = tid >> 4, c8 = tid & 15;
            *(uint4*)(Xs2 + r * 68 + c8 * 4) = v;
        }
        if (sw) asm volatile("cp.async.wait_group 0;");
        __syncthreads();    // X + B + bias ready

        // mainloop: all 4 gates per warp, no internal syncs
        float acc[4][2][4];
        #pragma unroll
        for (int g = 0; g < 4; g++)
            #pragma unroll
            for (int n = 0; n < 2; n++)
                #pragma unroll
                for (int j = 0; j < 4; j++) acc[g][n][j] = 0.f;

        const char* bB = smc + SM_B + (nq >> 2) * 2048 + (nq & 3) * 512 + lane * 16;
        #pragma unroll
        for (int ks = 0; ks < 8; ks++) {
            const uint32_t* xr = Xs2 + (mh * 16 + grp) * 68 + ks * 8 + tig;
            uint32_t a[4];
            a[0] = xr[0]; a[1] = xr[8 * 68]; a[2] = xr[4]; a[3] = xr[8 * 68 + 4];
            #pragma unroll
            for (int g = 0; g < 4; g++) {
                uint4 b = *(const uint4*)(bB + ks * 16384 + g * 4096);
                mma16(acc[g][0], a, b.x, b.y);
                mma16(acc[g][1], a, b.z, b.w);
            }
        }

        // register-only epilogue + direct store
        #pragma unroll
        for (int nt = 0; nt < 2; nt++) {
            #pragma unroll
            for (int half = 0; half < 2; half++) {
                int r = mh * 16 + grp + half * 8;
                float rs[2];
                #pragma unroll
                for (int jj = 0; jj < 2; jj++) {
                    int j = half * 2 + jj;
                    int c = nq * 16 + nt * 8 + tig * 2 + jj;
                    float v0 = acc[0][nt][j] + sbias[c];
                    float v1 = acc[1][nt][j] + sbias[128 + c];
                    float v2 = acc[2][nt][j] + sbias[256 + c];
                    float v3 = acc[3][nt][j] + sbias[384 + c];
                    uint32_t xp = Xs2[r * 68 + (c >> 1)];
                    __half2 xh = *(__half2*)&xp;
                    float xv = jj ? __half2float(__high2half(xh)) : __half2float(__low2half(xh));
                    float nres = xv * sigf(v0) + tanha(v1) * sigf(v2);
                    rs[jj] = tanha(nres) * sigf(v3);
                }
                int word = nq * 8 + nt * 4 + tig;
                if (L == 0) {
                    g_Xmid[(size_t)t * 4096 + r * 64 + word] = packh2(rs[0], rs[1]);
                } else {
                    int tk = stok[r];
                    if (tk >= 0)
                        ((float2*)out)[(size_t)tk * 64 + word] = make_float2(rs[0], rs[1]);
                }
            }
        }
        __syncthreads();    // protect Xs2/stok for next tile
    }

    if (L == 1 && blockIdx.x == 0 && tid < 9) g_cnt[tid] = 0;   // reset for next launch
}

extern "C" void kernel_launch(void* const* d_in, const int* in_sizes, int n_in,
                              void* d_out, int out_size) {
    const int* pos = (const int*)d_in[0];
    const float* x = (const float*)d_in[1];
    const float* W = (const float*)d_in[2];
    const float* b = (const float*)d_in[3];
    float* out = (float*)d_out;
    (void)in_sizes; (void)n_in; (void)out_size;
    cudaFuncSetAttribute(k_layer<0>, cudaFuncAttributeMaxDynamicSharedMemorySize, SMEM_MAIN);
    cudaFuncSetAttribute(k_layer<1>, cudaFuncAttributeMaxDynamicSharedMemorySize, SMEM_MAIN);
    k_prep_all<<<416, 512>>>(W, pos);
    k_layer<0><<<NSM, 1024, SMEM_MAIN>>>(x, b, out);
    k_layer<1><<<NSM, 1024, SMEM_MAIN>>>(x, b, out);
}